// round 11
// baseline (speedup 1.0000x reference)
#include <cuda_runtime.h>
#include <cuda_fp16.h>
#include <cstdint>

#define NN 100000
#define EE 1600000
#define TOTE (NN + EE)

// ---------------- static device scratch (allocation-free, zero-init) ----------------
__device__ int                g_rowptr[NN + 1];
__device__ int                g_cnt[NN];          // histogram; reset by k_scan for next replay
__device__ int                g_cur[NN];          // scatter cursor
__device__ float              g_dis[NN];          // rsqrt(deg)
__device__ float2             g_axw[NN];          // {A_hat x, A_hat 1} per node (atomic-built)
__device__ unsigned long long g_edge[TOTE];       // packed {src(int32) | normbits<<32}
__device__ uint4              g_bufA[NN * 4];     // z buffer   (fp16 rows, 64B/node)
__device__ uint4              g_bufB[NN * 4];     // agg buffer (fp16 rows, 64B/node)

__device__ __forceinline__ unsigned long long pack_edge(int c, float w) {
    return (unsigned long long)(unsigned)c |
           ((unsigned long long)__float_as_uint(w) << 32);
}

__device__ __forceinline__ uint32_t packh2(float a, float b) {
    __half2 h = __floats2half2_rn(a, b);
    return *reinterpret_cast<uint32_t*>(&h);
}

__device__ __forceinline__ void mma16816(float c[4], const uint32_t a[4], const uint32_t b[2]) {
    asm volatile("mma.sync.aligned.m16n8k16.row.col.f32.f16.f16.f32 "
                 "{%0,%1,%2,%3},{%4,%5,%6,%7},{%8,%9},{%0,%1,%2,%3};"
                 : "+f"(c[0]), "+f"(c[1]), "+f"(c[2]), "+f"(c[3])
                 : "r"(a[0]), "r"(a[1]), "r"(a[2]), "r"(a[3]), "r"(b[0]), "r"(b[1]));
}

// ---------------- preprocessing ----------------
__global__ void k_hist(const int* __restrict__ ei, int E) {
    int e = blockIdx.x * blockDim.x + threadIdx.x;
    if (e < E) atomicAdd(&g_cnt[ei[E + e]], 1);
}

__global__ void k_scan(const float* __restrict__ x, int n) {
    __shared__ int warpsum[32];
    __shared__ int chunkbase;
    const int tid = threadIdx.x, lane = tid & 31, wid = tid >> 5;
    if (tid == 0) chunkbase = 0;
    __syncthreads();
    for (int base = 0; base < n; base += 1024) {
        int i = base + tid;
        int ecnt = (i < n) ? g_cnt[i] : 0;
        if (i < n) g_cnt[i] = 0;                   // reset for next replay
        int v = ecnt + 1;                          // + self-loop
        int s = v;
#pragma unroll
        for (int d = 1; d < 32; d <<= 1) {
            int t = __shfl_up_sync(0xffffffffu, s, d);
            if (lane >= d) s += t;
        }
        if (lane == 31) warpsum[wid] = s;
        __syncthreads();
        if (wid == 0) {
            int ws = warpsum[lane];
#pragma unroll
            for (int d = 1; d < 32; d <<= 1) {
                int t = __shfl_up_sync(0xffffffffu, ws, d);
                if (lane >= d) ws += t;
            }
            warpsum[lane] = ws;
        }
        __syncthreads();
        int excl = chunkbase + s - v + (wid ? warpsum[wid - 1] : 0);
        if (i < n) {
            g_rowptr[i] = excl;
            float dv = rsqrtf((float)v);
            float dvdv = dv * dv;
            g_dis[i] = dv;
            g_edge[excl] = pack_edge(i, dvdv);     // self-loop edge first in row
            g_cur[i] = excl + 1;
            g_axw[i] = make_float2(dvdv * __ldg(&x[i]), dvdv);  // self-loop seed
        }
        __syncthreads();
        if (tid == 0) chunkbase += warpsum[31];
        __syncthreads();
    }
    if (tid == 0) g_rowptr[n] = chunkbase;
}

// fused: edge scatter (+atomic A_hat x / A_hat 1) AND per-node init producing
// z1 = h_init @ W1a directly (h_init = relu(fc2(relu(fc1(y0))))).
__global__ void k_scatter_pre(const int* __restrict__ ei, int E,
                              const float* __restrict__ x, const float* __restrict__ y,
                              const float* __restrict__ fc1W, const float* __restrict__ fc1b,
                              const float* __restrict__ fc2W, const float* __restrict__ fc2b,
                              const float* __restrict__ c1W,
                              float* __restrict__ out, int n) {
    __shared__ float s1W[32], s1b[32], s2W[32 * 26], s2b[26], sW1a[26 * 32];
    for (int i = threadIdx.x; i < 32; i += blockDim.x) { s1W[i] = fc1W[i]; s1b[i] = fc1b[i]; }
    for (int i = threadIdx.x; i < 32 * 26; i += blockDim.x) { s2W[i] = fc2W[i]; sW1a[i] = c1W[i]; }
    for (int i = threadIdx.x; i < 26; i += blockDim.x) s2b[i] = fc2b[i];
    __syncthreads();
    uint2* bufz = reinterpret_cast<uint2*>(g_bufA);
    int total = n + E;
    int stride = gridDim.x * blockDim.x;
    for (int g = blockIdx.x * blockDim.x + threadIdx.x; g < total; g += stride) {
        if (g < n) {
            int i = g;
            float y0 = y[i];
            out[i] = y0;
            float h0[32];
#pragma unroll
            for (int j = 0; j < 32; j++) h0[j] = fmaxf(fmaf(y0, s1W[j], s1b[j]), 0.f);
            float h26[26];
#pragma unroll
            for (int j = 0; j < 26; j++) {
                float s = s2b[j];
#pragma unroll
                for (int k = 0; k < 32; k++) s = fmaf(h0[k], s2W[k * 26 + j], s);
                h26[j] = fmaxf(s, 0.f);
            }
            float z[32];
#pragma unroll
            for (int j = 0; j < 32; j++) {
                float s = 0.f;
#pragma unroll
                for (int k = 0; k < 26; k++) s = fmaf(h26[k], sW1a[k * 32 + j], s);
                z[j] = s;
            }
#pragma unroll
            for (int q = 0; q < 8; q++) {
                uint2 pk;
                pk.x = packh2(z[4 * q], z[4 * q + 1]);
                pk.y = packh2(z[4 * q + 2], z[4 * q + 3]);
                bufz[i * 8 + q] = pk;
            }
        } else {
            int e = g - n;
            int s = ei[e];
            int d = ei[E + e];
            float w = g_dis[s] * g_dis[d];
            int pos = atomicAdd(&g_cur[d], 1);
            g_edge[pos] = pack_edge(s, w);
            atomicAdd(&g_axw[d].x, w * __ldg(&x[s]));
            atomicAdd(&g_axw[d].y, w);
        }
    }
}

// ---------------- SpMM: agg = A_hat @ z  (raw, no bias/relu) ----------------
// Smem edge staging (1 LDS.64 per gathered edge), phase-A burst (MLP 4),
// exact phase B, smem transpose-reduce.
// CORR (conv1 only): v[j] += ax*wx[j] + (aone*t)*wt[j]  (folded x/t columns)
template <bool CORR>
__global__ __launch_bounds__(256, 6)
void k_spmm(const float* __restrict__ W1, const float* __restrict__ tarr, int trow, int n) {
    constexpr unsigned FULL = 0xffffffffu;
    __shared__ __align__(16) float swx[32], swt[32];
    __shared__ __align__(16) float red[8][128];                  // per-warp 4x32 transpose buffer
    __shared__ __align__(16) unsigned long long sedge[8][32];    // per-warp edge staging
    const int tid = threadIdx.x, lane = tid & 31, w = tid >> 5;
    if constexpr (CORR) {
        if (tid < 32) {
            swx[tid] = W1[26 * 32 + tid] + W1[27 * 32 + tid] + W1[28 * 32 + tid];
            swt[tid] = W1[29 * 32 + tid] + W1[30 * 32 + tid] + W1[31 * 32 + tid];
        }
        __syncthreads();
    }
    const int eg = lane >> 3, f = lane & 7;
    const uint2* __restrict__ zin = reinterpret_cast<const uint2*>(g_bufA);
    __half2* __restrict__ aggout2 = reinterpret_cast<__half2*>(g_bufB);
    float wxl = 0.f, wtl = 0.f, tval = 0.f;
    if constexpr (CORR) {
        wxl = swx[lane]; wtl = swt[lane];
        tval = __ldg(&tarr[trow]);
    }
    const int gwid = (blockIdx.x * blockDim.x + tid) >> 5;
    const int nw   = (gridDim.x * blockDim.x) >> 5;
    const int CH   = (n + nw - 1) / nw;                // contiguous chunk per warp (<=31!)
    int base = gwid * CH;
    if (base >= n) return;
    int lim = n - base; if (lim > CH) lim = CH;
    int rp = __ldg(&g_rowptr[base + ((lane < lim) ? lane : lim)]);
    float* myred = red[w];
    unsigned long long* myedge = sedge[w];

    for (int i = 0; i < lim; i++) {
        int beg = __shfl_sync(FULL, rp, i);
        int end = __shfl_sync(FULL, rp, i + 1);
        int deg = end - beg;
        // preload up to 32 edges with one warp-wide LDG, stage into smem
        int eidx = beg + lane;
        unsigned long long ev = __ldg(&g_edge[(eidx < end) ? eidx : end - 1]);
        myedge[lane] = ev;
        __syncwarp();
        int dlim = (deg < 32) ? deg : 32;

        float4 acc = make_float4(0.f, 0.f, 0.f, 0.f);
        // ---- phase A: 16 edge slots, 4 independent LDS.64+LDG.64 chains ----
        uint2 rg[4]; float wg[4];
#pragma unroll
        for (int k = 0; k < 4; k++) {
            int j = eg + k * 4;
            unsigned long long e = myedge[j];          // 1 LDS.64: {src, wgt}
            float wgt = __uint_as_float((unsigned)(e >> 32));
            int   src = (int)(unsigned)e;
            wg[k] = (j < dlim) ? wgt : 0.f;
            rg[k] = __ldg(&zin[src * 8 + f]);          // clamped src: valid row, wgt=0
        }
#pragma unroll
        for (int k = 0; k < 4; k++) {
            float2 p0 = __half22float2(*reinterpret_cast<const __half2*>(&rg[k].x));
            float2 p1 = __half22float2(*reinterpret_cast<const __half2*>(&rg[k].y));
            acc.x = fmaf(wg[k], p0.x, acc.x);
            acc.y = fmaf(wg[k], p0.y, acc.y);
            acc.z = fmaf(wg[k], p1.x, acc.z);
            acc.w = fmaf(wg[k], p1.y, acc.w);
        }
        // ---- phase B: exact, warp-uniform (deg 17..32) ----
        for (int jb = 16; jb < dlim; jb += 4) {
            int j = jb + eg;                            // j < 32 always
            unsigned long long e = myedge[j];
            float wgt = __uint_as_float((unsigned)(e >> 32));
            int   src = (int)(unsigned)e;
            wgt = (j < dlim) ? wgt : 0.f;
            uint2 raw = __ldg(&zin[src * 8 + f]);
            float2 p0 = __half22float2(*reinterpret_cast<const __half2*>(&raw.x));
            float2 p1 = __half22float2(*reinterpret_cast<const __half2*>(&raw.y));
            acc.x = fmaf(wgt, p0.x, acc.x);
            acc.y = fmaf(wgt, p0.y, acc.y);
            acc.z = fmaf(wgt, p1.x, acc.z);
            acc.w = fmaf(wgt, p1.y, acc.w);
        }
        // ---- rare tail: deg > 32 (direct from gmem; divergence OK) ----
        for (int e2 = beg + 32 + eg; e2 < end; e2 += 4) {
            unsigned long long v = __ldg(&g_edge[e2]);
            float wgt = __uint_as_float((unsigned)(v >> 32));
            int   src = (int)(unsigned)v;
            uint2 raw = __ldg(&zin[src * 8 + f]);
            float2 p0 = __half22float2(*reinterpret_cast<const __half2*>(&raw.x));
            float2 p1 = __half22float2(*reinterpret_cast<const __half2*>(&raw.y));
            acc.x = fmaf(wgt, p0.x, acc.x);
            acc.y = fmaf(wgt, p0.y, acc.y);
            acc.z = fmaf(wgt, p1.x, acc.z);
            acc.w = fmaf(wgt, p1.y, acc.w);
        }
        // ---- smem transpose-reduce: STS.128 + 4 LDS + 3 FADD ----
        *reinterpret_cast<float4*>(&myred[(eg * 8 + f) * 4]) = acc;
        __syncwarp();
        float v = myred[lane] + myred[32 + lane] + myred[64 + lane] + myred[96 + lane];
        __syncwarp();                               // protect red[]/sedge[] before next overwrite
        if constexpr (CORR) {
            float2 axw = __ldg(&g_axw[base + i]);
            v = fmaf(axw.x, wxl, fmaf(axw.y * tval, wtl, v));
        }
        // pack feature pairs -> half2; even lanes store 4B each (64B row)
        float vhi = __shfl_down_sync(FULL, v, 1);
        if ((lane & 1) == 0)
            aggout2[(base + i) * 16 + (lane >> 1)] = __floats2half2_rn(v, vhi);
    }
}

// ---------------- GEMM: z = relu(agg + b_prev) @ W~next, 16-node tiles, HMMA ----------
// KIND 0: b1, W2 (32x32). KIND 1: b2, W3 (32x26 padded). KIND 2: b3(26), W1a (26x32 padded)
//         + fused fc3/relu/fc4 head (A-frags ARE h3 -> reused directly).
template <int KIND>
__global__ __launch_bounds__(256)
void k_gemm(const float* __restrict__ bprev, const float* __restrict__ Wn,
            const float* __restrict__ f3W, const float* __restrict__ f3b,
            const float* __restrict__ f4W, const float* __restrict__ f4b,
            float* __restrict__ out, int trow, int n) {
    constexpr unsigned FULL = 0xffffffffu;
    constexpr int BPREV = (KIND == 2) ? 26 : 32;
    __shared__ __align__(16) __half sWt[32 * 40];
    __shared__ __align__(16) __half sW2[32 * 40];
    __shared__ __align__(16) __half sA[8][16 * 40];
    __shared__ __half2 sbh[16];
    __shared__ float sb3[32], sf4[32], sf4b;

    const int tid = threadIdx.x, lane = tid & 31, w = tid >> 5;

    for (int i = tid; i < 1024; i += blockDim.x) {
        int k = i >> 5, j = i & 31;
        float v;
        if constexpr (KIND == 0)      v = Wn[k * 32 + j];
        else if constexpr (KIND == 1) v = (j < 26) ? Wn[k * 26 + j] : 0.f;
        else                          v = (k < 26) ? Wn[k * 32 + j] : 0.f;
        sWt[k * 40 + j] = __float2half(v);
        if constexpr (KIND == 2)
            sW2[k * 40 + j] = __float2half((k < 26) ? f3W[k * 32 + j] : 0.f);
    }
    if (tid < 16) {
        float b0 = (2 * tid < BPREV)     ? bprev[2 * tid]     : 0.f;
        float b1 = (2 * tid + 1 < BPREV) ? bprev[2 * tid + 1] : 0.f;
        sbh[tid] = __floats2half2_rn(b0, b1);
    }
    if constexpr (KIND == 2) {
        if (tid < 32) { sb3[tid] = f3b[tid]; sf4[tid] = f4W[tid]; }
        if (tid == 0) sf4b = f4b[0];
    }
    __syncthreads();

    uint32_t bf[2][4][2], bf2[2][4][2];
    {
        int r = lane & 15;
#pragma unroll
        for (int s = 0; s < 2; s++)
#pragma unroll
            for (int t = 0; t < 4; t++) {
                uint32_t addr = (uint32_t)__cvta_generic_to_shared(&sWt[(s * 16 + r) * 40 + t * 8]);
                asm volatile("ldmatrix.sync.aligned.m8n8.x2.trans.shared.b16 {%0,%1},[%2];"
                             : "=r"(bf[s][t][0]), "=r"(bf[s][t][1]) : "r"(addr));
                if constexpr (KIND == 2) {
                    uint32_t a2 = (uint32_t)__cvta_generic_to_shared(&sW2[(s * 16 + r) * 40 + t * 8]);
                    asm volatile("ldmatrix.sync.aligned.m8n8.x2.trans.shared.b16 {%0,%1},[%2];"
                                 : "=r"(bf2[s][t][0]), "=r"(bf2[s][t][1]) : "r"(a2));
                }
            }
    }
    const int tig = lane & 3, grp = lane >> 2;
    float b3r[8], wf4[8], b4 = 0.f;
    if constexpr (KIND == 2) {
#pragma unroll
        for (int t = 0; t < 4; t++) {
            b3r[t * 2]     = sb3[t * 8 + tig * 2];
            b3r[t * 2 + 1] = sb3[t * 8 + tig * 2 + 1];
            wf4[t * 2]     = sf4[t * 8 + tig * 2];
            wf4[t * 2 + 1] = sf4[t * 8 + tig * 2 + 1];
        }
        b4 = sf4b;
    }

    const uint4* __restrict__ agg4 = g_bufB;
    __half2* __restrict__ zout = reinterpret_cast<__half2*>(g_bufA);
    const int gwid = (blockIdx.x * blockDim.x + tid) >> 5;
    const int nw   = (gridDim.x * blockDim.x) >> 5;
    const uint32_t abase = (uint32_t)__cvta_generic_to_shared(&sA[w][0]);
    const __half2 zero2 = __float2half2_rn(0.f);

    for (int nb = gwid * 16; nb < n; nb += nw * 16) {
        __syncwarp();
        int row = lane >> 1, c = lane & 1;
        int r = nb + row;
        uint4 v0 = make_uint4(0, 0, 0, 0), v1 = make_uint4(0, 0, 0, 0);
        if (r < n) {
            v0 = __ldg(&agg4[r * 4 + 2 * c]);
            v1 = __ldg(&agg4[r * 4 + 2 * c + 1]);
        }
        // A = relu(agg + b_prev), elementwise in half2
        {
            uint32_t* p = &v0.x;
#pragma unroll
            for (int q = 0; q < 4; q++) {
                __half2 h = *reinterpret_cast<__half2*>(&p[q]);
                h = __hmax2(__hadd2(h, sbh[(2 * c) * 4 + q]), zero2);
                p[q] = *reinterpret_cast<uint32_t*>(&h);
            }
            uint32_t* p2 = &v1.x;
#pragma unroll
            for (int q = 0; q < 4; q++) {
                __half2 h = *reinterpret_cast<__half2*>(&p2[q]);
                h = __hmax2(__hadd2(h, sbh[(2 * c + 1) * 4 + q]), zero2);
                p2[q] = *reinterpret_cast<uint32_t*>(&h);
            }
        }
        char* rowbase = reinterpret_cast<char*>(&sA[w][0]) + row * 80;
        *reinterpret_cast<uint4*>(rowbase + (2 * c) * 16)     = v0;
        *reinterpret_cast<uint4*>(rowbase + (2 * c + 1) * 16) = v1;
        __syncwarp();

        uint32_t af[2][4];
#pragma unroll
        for (int s = 0; s < 2; s++) {
            int g2 = lane >> 3;
            uint32_t addr = abase + ((lane & 7) + (g2 & 1) * 8) * 80 + s * 32 + (g2 >> 1) * 16;
            asm volatile("ldmatrix.sync.aligned.m8n8.x4.shared.b16 {%0,%1,%2,%3},[%4];"
                         : "=r"(af[s][0]), "=r"(af[s][1]), "=r"(af[s][2]), "=r"(af[s][3])
                         : "r"(addr));
        }

        float z[4][4];
#pragma unroll
        for (int t = 0; t < 4; t++) { z[t][0] = 0.f; z[t][1] = 0.f; z[t][2] = 0.f; z[t][3] = 0.f; }
#pragma unroll
        for (int s = 0; s < 2; s++)
#pragma unroll
            for (int t = 0; t < 4; t++)
                mma16816(z[t], af[s], bf[s][t]);

        int r0 = nb + grp, r1 = nb + grp + 8;
        bool ok0 = r0 < n, ok1 = r1 < n;
#pragma unroll
        for (int t = 0; t < 4; t++) {
            __half2 p0 = __floats2half2_rn(z[t][0], z[t][1]);
            __half2 p1 = __floats2half2_rn(z[t][2], z[t][3]);
            if (ok0) zout[r0 * 16 + t * 4 + tig] = p0;
            if (ok1) zout[r1 * 16 + t * 4 + tig] = p1;
        }

        if constexpr (KIND == 2) {
            float zz[4][4];
#pragma unroll
            for (int t = 0; t < 4; t++) {
                zz[t][0] = b3r[t * 2];   zz[t][1] = b3r[t * 2 + 1];
                zz[t][2] = b3r[t * 2];   zz[t][3] = b3r[t * 2 + 1];
            }
#pragma unroll
            for (int s = 0; s < 2; s++)
#pragma unroll
                for (int t = 0; t < 4; t++)
                    mma16816(zz[t], af[s], bf2[s][t]);
            float p0 = 0.f, p1 = 0.f;
#pragma unroll
            for (int t = 0; t < 4; t++) {
                p0 = fmaf(fmaxf(zz[t][0], 0.f), wf4[t * 2],     p0);
                p0 = fmaf(fmaxf(zz[t][1], 0.f), wf4[t * 2 + 1], p0);
                p1 = fmaf(fmaxf(zz[t][2], 0.f), wf4[t * 2],     p1);
                p1 = fmaf(fmaxf(zz[t][3], 0.f), wf4[t * 2 + 1], p1);
            }
            p0 += __shfl_xor_sync(FULL, p0, 1);
            p0 += __shfl_xor_sync(FULL, p0, 2);
            p1 += __shfl_xor_sync(FULL, p1, 1);
            p1 += __shfl_xor_sync(FULL, p1, 2);
            if (tig == 0) {
                long long ob = (long long)trow * n;
                if (ok0) out[ob + r0] = p0 + b4;
                if (ok1) out[ob + r1] = p1 + b4;
            }
        }
    }
}

// ---------------- launcher ----------------
extern "C" void kernel_launch(void* const* d_in, const int* in_sizes, int n_in,
                              void* d_out, int out_size) {
    const float* x    = (const float*)d_in[0];
    const float* t    = (const float*)d_in[1];
    const float* y    = (const float*)d_in[2];
    const int*   ei   = (const int*)d_in[3];     // int32 (JAX x64 disabled)
    const float* fc1W = (const float*)d_in[4],  *fc1b = (const float*)d_in[5];
    const float* fc2W = (const float*)d_in[6],  *fc2b = (const float*)d_in[7];
    const float* c1W  = (const float*)d_in[8],  *c1b  = (const float*)d_in[9];
    const float* c2W  = (const float*)d_in[10], *c2b  = (const float*)d_in[11];
    const float* c3W  = (const float*)d_in[12], *c3b  = (const float*)d_in[13];
    const float* fc3W = (const float*)d_in[14], *fc3b = (const float*)d_in[15];
    const float* fc4W = (const float*)d_in[16], *fc4b = (const float*)d_in[17];

    int n = in_sizes[0];          // N
    int T = in_sizes[1];          // timesteps
    int E = in_sizes[3] / 2;      // edges
    float* out = (float*)d_out;

    const int tb = 256;
    k_hist<<<(E + tb - 1) / tb, tb>>>(ei, E);                      // launch 1
    k_scan<<<1, 1024>>>(x, n);                                     // launch 2
    k_scatter_pre<<<(n + E + tb - 1) / tb, tb>>>(ei, E, x, y,      // launch 3
                                                 fc1W, fc1b, fc2W, fc2b, c1W, out, n);

    const int CB_S = 888;   // spmm: 148 SMs x 6 resident blocks -> 48 warps/SM
    const int CB_G = 740;   // gemm: memory-floor, unchanged
    for (int r = 1; r < T; r++) {
        k_spmm<true><<<CB_S, 256>>>(c1W, t, r, n);                            // launch 4 = profiled
        k_gemm<0><<<CB_G, 256>>>(c1b, c2W, nullptr, nullptr, nullptr, nullptr, nullptr, 0, n);
        k_spmm<false><<<CB_S, 256>>>(nullptr, nullptr, 0, n);
        k_gemm<1><<<CB_G, 256>>>(c2b, c3W, nullptr, nullptr, nullptr, nullptr, nullptr, 0, n);
        k_spmm<false><<<CB_S, 256>>>(nullptr, nullptr, 0, n);
        k_gemm<2><<<CB_G, 256>>>(c3b, c1W, fc3W, fc3b, fc4W, fc4b, out, r, n);  // + head
    }
}

// round 12
// speedup vs baseline: 1.2174x; 1.2174x over previous
#include <cuda_runtime.h>
#include <cuda_fp16.h>
#include <cstdint>

#define NN 100000
#define EE 1600000
#define TOTE (NN + EE)

// ---------------- static device scratch (allocation-free, zero-init) ----------------
__device__ int                g_rowptr[NN + 1];
__device__ int                g_cnt[NN];          // histogram; reset by k_scan for next replay
__device__ int                g_cur[NN];          // scatter cursor
__device__ float              g_dis[NN];          // rsqrt(deg)
__device__ float2             g_axw[NN];          // {A_hat x, A_hat 1} per node (atomic-built)
__device__ unsigned long long g_edge[TOTE];       // packed {src(int32) | normbits<<32}
__device__ uint4              g_bufA[NN * 4];     // z buffer   (fp16 rows, 64B/node)
__device__ uint4              g_bufB[NN * 4];     // agg buffer (fp16 rows, 64B/node)

__device__ __forceinline__ unsigned long long pack_edge(int c, float w) {
    return (unsigned long long)(unsigned)c |
           ((unsigned long long)__float_as_uint(w) << 32);
}

__device__ __forceinline__ uint32_t packh2(float a, float b) {
    __half2 h = __floats2half2_rn(a, b);
    return *reinterpret_cast<uint32_t*>(&h);
}

__device__ __forceinline__ void mma16816(float c[4], const uint32_t a[4], const uint32_t b[2]) {
    asm volatile("mma.sync.aligned.m16n8k16.row.col.f32.f16.f16.f32 "
                 "{%0,%1,%2,%3},{%4,%5,%6,%7},{%8,%9},{%0,%1,%2,%3};"
                 : "+f"(c[0]), "+f"(c[1]), "+f"(c[2]), "+f"(c[3])
                 : "r"(a[0]), "r"(a[1]), "r"(a[2]), "r"(a[3]), "r"(b[0]), "r"(b[1]));
}

// ---------------- preprocessing ----------------
__global__ void k_hist(const int* __restrict__ ei, int E) {
    int e = blockIdx.x * blockDim.x + threadIdx.x;
    if (e < E) atomicAdd(&g_cnt[ei[E + e]], 1);
}

__global__ void k_scan(const float* __restrict__ x, int n) {
    __shared__ int warpsum[32];
    __shared__ int chunkbase;
    const int tid = threadIdx.x, lane = tid & 31, wid = tid >> 5;
    if (tid == 0) chunkbase = 0;
    __syncthreads();
    for (int base = 0; base < n; base += 1024) {
        int i = base + tid;
        int ecnt = (i < n) ? g_cnt[i] : 0;
        if (i < n) g_cnt[i] = 0;                   // reset for next replay
        int v = ecnt + 1;                          // + self-loop
        int s = v;
#pragma unroll
        for (int d = 1; d < 32; d <<= 1) {
            int t = __shfl_up_sync(0xffffffffu, s, d);
            if (lane >= d) s += t;
        }
        if (lane == 31) warpsum[wid] = s;
        __syncthreads();
        if (wid == 0) {
            int ws = warpsum[lane];
#pragma unroll
            for (int d = 1; d < 32; d <<= 1) {
                int t = __shfl_up_sync(0xffffffffu, ws, d);
                if (lane >= d) ws += t;
            }
            warpsum[lane] = ws;
        }
        __syncthreads();
        int excl = chunkbase + s - v + (wid ? warpsum[wid - 1] : 0);
        if (i < n) {
            g_rowptr[i] = excl;
            float dv = rsqrtf((float)v);
            float dvdv = dv * dv;
            g_dis[i] = dv;
            g_edge[excl] = pack_edge(i, dvdv);     // self-loop edge first in row
            g_cur[i] = excl + 1;
            g_axw[i] = make_float2(dvdv * __ldg(&x[i]), dvdv);  // self-loop seed
        }
        __syncthreads();
        if (tid == 0) chunkbase += warpsum[31];
        __syncthreads();
    }
    if (tid == 0) g_rowptr[n] = chunkbase;
}

// fused: edge scatter (+atomic A_hat x / A_hat 1) AND per-node init producing
// z1 = h_init @ W1a directly (h_init = relu(fc2(relu(fc1(y0))))).
__global__ void k_scatter_pre(const int* __restrict__ ei, int E,
                              const float* __restrict__ x, const float* __restrict__ y,
                              const float* __restrict__ fc1W, const float* __restrict__ fc1b,
                              const float* __restrict__ fc2W, const float* __restrict__ fc2b,
                              const float* __restrict__ c1W,
                              float* __restrict__ out, int n) {
    __shared__ float s1W[32], s1b[32], s2W[32 * 26], s2b[26], sW1a[26 * 32];
    for (int i = threadIdx.x; i < 32; i += blockDim.x) { s1W[i] = fc1W[i]; s1b[i] = fc1b[i]; }
    for (int i = threadIdx.x; i < 32 * 26; i += blockDim.x) { s2W[i] = fc2W[i]; sW1a[i] = c1W[i]; }
    for (int i = threadIdx.x; i < 26; i += blockDim.x) s2b[i] = fc2b[i];
    __syncthreads();
    uint2* bufz = reinterpret_cast<uint2*>(g_bufA);
    int total = n + E;
    int stride = gridDim.x * blockDim.x;
    for (int g = blockIdx.x * blockDim.x + threadIdx.x; g < total; g += stride) {
        if (g < n) {
            int i = g;
            float y0 = y[i];
            out[i] = y0;
            float h0[32];
#pragma unroll
            for (int j = 0; j < 32; j++) h0[j] = fmaxf(fmaf(y0, s1W[j], s1b[j]), 0.f);
            float h26[26];
#pragma unroll
            for (int j = 0; j < 26; j++) {
                float s = s2b[j];
#pragma unroll
                for (int k = 0; k < 32; k++) s = fmaf(h0[k], s2W[k * 26 + j], s);
                h26[j] = fmaxf(s, 0.f);
            }
            float z[32];
#pragma unroll
            for (int j = 0; j < 32; j++) {
                float s = 0.f;
#pragma unroll
                for (int k = 0; k < 26; k++) s = fmaf(h26[k], sW1a[k * 32 + j], s);
                z[j] = s;
            }
#pragma unroll
            for (int q = 0; q < 8; q++) {
                uint2 pk;
                pk.x = packh2(z[4 * q], z[4 * q + 1]);
                pk.y = packh2(z[4 * q + 2], z[4 * q + 3]);
                bufz[i * 8 + q] = pk;
            }
        } else {
            int e = g - n;
            int s = ei[e];
            int d = ei[E + e];
            float w = g_dis[s] * g_dis[d];
            int pos = atomicAdd(&g_cur[d], 1);
            g_edge[pos] = pack_edge(s, w);
            atomicAdd(&g_axw[d].x, w * __ldg(&x[s]));
            atomicAdd(&g_axw[d].y, w);
        }
    }
}

// ---------------- SpMM: agg = A_hat @ z  (raw, no bias/relu) ----------------
// Shuffle-broadcast edges (R10 design), phase-A burst gather (MLP 4),
// exact phase B, smem transpose-reduce. Grid sized for 6 blocks/SM residency.
// CORR (conv1 only): v[j] += ax*wx[j] + (aone*t)*wt[j]  (folded x/t columns)
template <bool CORR>
__global__ __launch_bounds__(256, 6)
void k_spmm(const float* __restrict__ W1, const float* __restrict__ tarr, int trow, int n) {
    constexpr unsigned FULL = 0xffffffffu;
    __shared__ __align__(16) float swx[32], swt[32];
    __shared__ __align__(16) float red[8][128];     // per-warp 4x32 transpose buffer
    const int tid = threadIdx.x, lane = tid & 31, w = tid >> 5;
    if constexpr (CORR) {
        if (tid < 32) {
            swx[tid] = W1[26 * 32 + tid] + W1[27 * 32 + tid] + W1[28 * 32 + tid];
            swt[tid] = W1[29 * 32 + tid] + W1[30 * 32 + tid] + W1[31 * 32 + tid];
        }
        __syncthreads();
    }
    const int eg = lane >> 3, f = lane & 7;
    const uint2* __restrict__ zin = reinterpret_cast<const uint2*>(g_bufA);
    __half2* __restrict__ aggout2 = reinterpret_cast<__half2*>(g_bufB);
    float wxl = 0.f, wtl = 0.f, tval = 0.f;
    if constexpr (CORR) {
        wxl = swx[lane]; wtl = swt[lane];
        tval = __ldg(&tarr[trow]);
    }
    const int gwid = (blockIdx.x * blockDim.x + tid) >> 5;
    const int nw   = (gridDim.x * blockDim.x) >> 5;
    const int CH   = (n + nw - 1) / nw;                // contiguous chunk per warp (<=31!)
    int base = gwid * CH;
    if (base >= n) return;
    int lim = n - base; if (lim > CH) lim = CH;
    int rp = __ldg(&g_rowptr[base + ((lane < lim) ? lane : lim)]);
    float* myred = red[w];

    for (int i = 0; i < lim; i++) {
        int beg = __shfl_sync(FULL, rp, i);
        int end = __shfl_sync(FULL, rp, i + 1);
        int deg = end - beg;
        // preload up to 32 edges with one warp-wide LDG
        int eidx = beg + lane;
        unsigned long long ev = __ldg(&g_edge[(eidx < end) ? eidx : end - 1]);
        float ew  = __uint_as_float((unsigned)(ev >> 32));
        int  esrc = (int)(unsigned)ev;
        int dlim = (deg < 32) ? deg : 32;

        float4 acc = make_float4(0.f, 0.f, 0.f, 0.f);
        // ---- phase A: 16 edge slots, 4 independent LDGs in flight ----
        uint2 rg[4]; float wg[4];
#pragma unroll
        for (int k = 0; k < 4; k++) {
            int j = eg + k * 4;
            float wgt = __shfl_sync(FULL, ew, j & 31);
            int   src = __shfl_sync(FULL, esrc, j & 31);
            wg[k] = (j < dlim) ? wgt : 0.f;
            rg[k] = __ldg(&zin[src * 8 + f]);      // clamped src: valid row, wgt=0
        }
#pragma unroll
        for (int k = 0; k < 4; k++) {
            float2 p0 = __half22float2(*reinterpret_cast<const __half2*>(&rg[k].x));
            float2 p1 = __half22float2(*reinterpret_cast<const __half2*>(&rg[k].y));
            acc.x = fmaf(wg[k], p0.x, acc.x);
            acc.y = fmaf(wg[k], p0.y, acc.y);
            acc.z = fmaf(wg[k], p1.x, acc.z);
            acc.w = fmaf(wg[k], p1.y, acc.w);
        }
        // ---- phase B: exact, warp-uniform (deg 17..32) ----
        for (int jb = 16; jb < dlim; jb += 4) {
            int j = jb + eg;
            float wgt = __shfl_sync(FULL, ew, j & 31);
            int   src = __shfl_sync(FULL, esrc, j & 31);
            wgt = (j < dlim) ? wgt : 0.f;
            uint2 raw = __ldg(&zin[src * 8 + f]);
            float2 p0 = __half22float2(*reinterpret_cast<const __half2*>(&raw.x));
            float2 p1 = __half22float2(*reinterpret_cast<const __half2*>(&raw.y));
            acc.x = fmaf(wgt, p0.x, acc.x);
            acc.y = fmaf(wgt, p0.y, acc.y);
            acc.z = fmaf(wgt, p1.x, acc.z);
            acc.w = fmaf(wgt, p1.y, acc.w);
        }
        // ---- rare tail: deg > 32 (no warp-sync primitives; divergence OK) ----
        for (int e2 = beg + 32 + eg; e2 < end; e2 += 4) {
            unsigned long long v = __ldg(&g_edge[e2]);
            float wgt = __uint_as_float((unsigned)(v >> 32));
            int   src = (int)(unsigned)v;
            uint2 raw = __ldg(&zin[src * 8 + f]);
            float2 p0 = __half22float2(*reinterpret_cast<const __half2*>(&raw.x));
            float2 p1 = __half22float2(*reinterpret_cast<const __half2*>(&raw.y));
            acc.x = fmaf(wgt, p0.x, acc.x);
            acc.y = fmaf(wgt, p0.y, acc.y);
            acc.z = fmaf(wgt, p1.x, acc.z);
            acc.w = fmaf(wgt, p1.y, acc.w);
        }
        // ---- smem transpose-reduce: STS.128 + 4 LDS + 3 FADD ----
        *reinterpret_cast<float4*>(&myred[(eg * 8 + f) * 4]) = acc;
        __syncwarp();
        float v = myred[lane] + myred[32 + lane] + myred[64 + lane] + myred[96 + lane];
        __syncwarp();                               // protect red[] before next overwrite
        if constexpr (CORR) {
            float2 axw = __ldg(&g_axw[base + i]);
            v = fmaf(axw.x, wxl, fmaf(axw.y * tval, wtl, v));
        }
        // pack feature pairs -> half2; even lanes store 4B each (64B row)
        float vhi = __shfl_down_sync(FULL, v, 1);
        if ((lane & 1) == 0)
            aggout2[(base + i) * 16 + (lane >> 1)] = __floats2half2_rn(v, vhi);
    }
}

// ---------------- GEMM: z = relu(agg + b_prev) @ W~next, 16-node tiles, HMMA ----------
// KIND 0: b1, W2 (32x32). KIND 1: b2, W3 (32x26 padded). KIND 2: b3(26), W1a (26x32 padded)
//         + fused fc3/relu/fc4 head (A-frags ARE h3 -> reused directly).
template <int KIND>
__global__ __launch_bounds__(256)
void k_gemm(const float* __restrict__ bprev, const float* __restrict__ Wn,
            const float* __restrict__ f3W, const float* __restrict__ f3b,
            const float* __restrict__ f4W, const float* __restrict__ f4b,
            float* __restrict__ out, int trow, int n) {
    constexpr unsigned FULL = 0xffffffffu;
    constexpr int BPREV = (KIND == 2) ? 26 : 32;
    __shared__ __align__(16) __half sWt[32 * 40];
    __shared__ __align__(16) __half sW2[32 * 40];
    __shared__ __align__(16) __half sA[8][16 * 40];
    __shared__ __half2 sbh[16];
    __shared__ float sb3[32], sf4[32], sf4b;

    const int tid = threadIdx.x, lane = tid & 31, w = tid >> 5;

    for (int i = tid; i < 1024; i += blockDim.x) {
        int k = i >> 5, j = i & 31;
        float v;
        if constexpr (KIND == 0)      v = Wn[k * 32 + j];
        else if constexpr (KIND == 1) v = (j < 26) ? Wn[k * 26 + j] : 0.f;
        else                          v = (k < 26) ? Wn[k * 32 + j] : 0.f;
        sWt[k * 40 + j] = __float2half(v);
        if constexpr (KIND == 2)
            sW2[k * 40 + j] = __float2half((k < 26) ? f3W[k * 32 + j] : 0.f);
    }
    if (tid < 16) {
        float b0 = (2 * tid < BPREV)     ? bprev[2 * tid]     : 0.f;
        float b1 = (2 * tid + 1 < BPREV) ? bprev[2 * tid + 1] : 0.f;
        sbh[tid] = __floats2half2_rn(b0, b1);
    }
    if constexpr (KIND == 2) {
        if (tid < 32) { sb3[tid] = f3b[tid]; sf4[tid] = f4W[tid]; }
        if (tid == 0) sf4b = f4b[0];
    }
    __syncthreads();

    uint32_t bf[2][4][2], bf2[2][4][2];
    {
        int r = lane & 15;
#pragma unroll
        for (int s = 0; s < 2; s++)
#pragma unroll
            for (int t = 0; t < 4; t++) {
                uint32_t addr = (uint32_t)__cvta_generic_to_shared(&sWt[(s * 16 + r) * 40 + t * 8]);
                asm volatile("ldmatrix.sync.aligned.m8n8.x2.trans.shared.b16 {%0,%1},[%2];"
                             : "=r"(bf[s][t][0]), "=r"(bf[s][t][1]) : "r"(addr));
                if constexpr (KIND == 2) {
                    uint32_t a2 = (uint32_t)__cvta_generic_to_shared(&sW2[(s * 16 + r) * 40 + t * 8]);
                    asm volatile("ldmatrix.sync.aligned.m8n8.x2.trans.shared.b16 {%0,%1},[%2];"
                                 : "=r"(bf2[s][t][0]), "=r"(bf2[s][t][1]) : "r"(a2));
                }
            }
    }
    const int tig = lane & 3, grp = lane >> 2;
    float b3r[8], wf4[8], b4 = 0.f;
    if constexpr (KIND == 2) {
#pragma unroll
        for (int t = 0; t < 4; t++) {
            b3r[t * 2]     = sb3[t * 8 + tig * 2];
            b3r[t * 2 + 1] = sb3[t * 8 + tig * 2 + 1];
            wf4[t * 2]     = sf4[t * 8 + tig * 2];
            wf4[t * 2 + 1] = sf4[t * 8 + tig * 2 + 1];
        }
        b4 = sf4b;
    }

    const uint4* __restrict__ agg4 = g_bufB;
    __half2* __restrict__ zout = reinterpret_cast<__half2*>(g_bufA);
    const int gwid = (blockIdx.x * blockDim.x + tid) >> 5;
    const int nw   = (gridDim.x * blockDim.x) >> 5;
    const uint32_t abase = (uint32_t)__cvta_generic_to_shared(&sA[w][0]);
    const __half2 zero2 = __float2half2_rn(0.f);

    for (int nb = gwid * 16; nb < n; nb += nw * 16) {
        __syncwarp();
        int row = lane >> 1, c = lane & 1;
        int r = nb + row;
        uint4 v0 = make_uint4(0, 0, 0, 0), v1 = make_uint4(0, 0, 0, 0);
        if (r < n) {
            v0 = __ldg(&agg4[r * 4 + 2 * c]);
            v1 = __ldg(&agg4[r * 4 + 2 * c + 1]);
        }
        // A = relu(agg + b_prev), elementwise in half2
        {
            uint32_t* p = &v0.x;
#pragma unroll
            for (int q = 0; q < 4; q++) {
                __half2 h = *reinterpret_cast<__half2*>(&p[q]);
                h = __hmax2(__hadd2(h, sbh[(2 * c) * 4 + q]), zero2);
                p[q] = *reinterpret_cast<uint32_t*>(&h);
            }
            uint32_t* p2 = &v1.x;
#pragma unroll
            for (int q = 0; q < 4; q++) {
                __half2 h = *reinterpret_cast<__half2*>(&p2[q]);
                h = __hmax2(__hadd2(h, sbh[(2 * c + 1) * 4 + q]), zero2);
                p2[q] = *reinterpret_cast<uint32_t*>(&h);
            }
        }
        char* rowbase = reinterpret_cast<char*>(&sA[w][0]) + row * 80;
        *reinterpret_cast<uint4*>(rowbase + (2 * c) * 16)     = v0;
        *reinterpret_cast<uint4*>(rowbase + (2 * c + 1) * 16) = v1;
        __syncwarp();

        uint32_t af[2][4];
#pragma unroll
        for (int s = 0; s < 2; s++) {
            int g2 = lane >> 3;
            uint32_t addr = abase + ((lane & 7) + (g2 & 1) * 8) * 80 + s * 32 + (g2 >> 1) * 16;
            asm volatile("ldmatrix.sync.aligned.m8n8.x4.shared.b16 {%0,%1,%2,%3},[%4];"
                         : "=r"(af[s][0]), "=r"(af[s][1]), "=r"(af[s][2]), "=r"(af[s][3])
                         : "r"(addr));
        }

        float z[4][4];
#pragma unroll
        for (int t = 0; t < 4; t++) { z[t][0] = 0.f; z[t][1] = 0.f; z[t][2] = 0.f; z[t][3] = 0.f; }
#pragma unroll
        for (int s = 0; s < 2; s++)
#pragma unroll
            for (int t = 0; t < 4; t++)
                mma16816(z[t], af[s], bf[s][t]);

        int r0 = nb + grp, r1 = nb + grp + 8;
        bool ok0 = r0 < n, ok1 = r1 < n;
#pragma unroll
        for (int t = 0; t < 4; t++) {
            __half2 p0 = __floats2half2_rn(z[t][0], z[t][1]);
            __half2 p1 = __floats2half2_rn(z[t][2], z[t][3]);
            if (ok0) zout[r0 * 16 + t * 4 + tig] = p0;
            if (ok1) zout[r1 * 16 + t * 4 + tig] = p1;
        }

        if constexpr (KIND == 2) {
            float zz[4][4];
#pragma unroll
            for (int t = 0; t < 4; t++) {
                zz[t][0] = b3r[t * 2];   zz[t][1] = b3r[t * 2 + 1];
                zz[t][2] = b3r[t * 2];   zz[t][3] = b3r[t * 2 + 1];
            }
#pragma unroll
            for (int s = 0; s < 2; s++)
#pragma unroll
                for (int t = 0; t < 4; t++)
                    mma16816(zz[t], af[s], bf2[s][t]);
            float p0 = 0.f, p1 = 0.f;
#pragma unroll
            for (int t = 0; t < 4; t++) {
                p0 = fmaf(fmaxf(zz[t][0], 0.f), wf4[t * 2],     p0);
                p0 = fmaf(fmaxf(zz[t][1], 0.f), wf4[t * 2 + 1], p0);
                p1 = fmaf(fmaxf(zz[t][2], 0.f), wf4[t * 2],     p1);
                p1 = fmaf(fmaxf(zz[t][3], 0.f), wf4[t * 2 + 1], p1);
            }
            p0 += __shfl_xor_sync(FULL, p0, 1);
            p0 += __shfl_xor_sync(FULL, p0, 2);
            p1 += __shfl_xor_sync(FULL, p1, 1);
            p1 += __shfl_xor_sync(FULL, p1, 2);
            if (tig == 0) {
                long long ob = (long long)trow * n;
                if (ok0) out[ob + r0] = p0 + b4;
                if (ok1) out[ob + r1] = p1 + b4;
            }
        }
    }
}

// ---------------- launcher ----------------
extern "C" void kernel_launch(void* const* d_in, const int* in_sizes, int n_in,
                              void* d_out, int out_size) {
    const float* x    = (const float*)d_in[0];
    const float* t    = (const float*)d_in[1];
    const float* y    = (const float*)d_in[2];
    const int*   ei   = (const int*)d_in[3];     // int32 (JAX x64 disabled)
    const float* fc1W = (const float*)d_in[4],  *fc1b = (const float*)d_in[5];
    const float* fc2W = (const float*)d_in[6],  *fc2b = (const float*)d_in[7];
    const float* c1W  = (const float*)d_in[8],  *c1b  = (const float*)d_in[9];
    const float* c2W  = (const float*)d_in[10], *c2b  = (const float*)d_in[11];
    const float* c3W  = (const float*)d_in[12], *c3b  = (const float*)d_in[13];
    const float* fc3W = (const float*)d_in[14], *fc3b = (const float*)d_in[15];
    const float* fc4W = (const float*)d_in[16], *fc4b = (const float*)d_in[17];

    int n = in_sizes[0];          // N
    int T = in_sizes[1];          // timesteps
    int E = in_sizes[3] / 2;      // edges
    float* out = (float*)d_out;

    const int tb = 256;
    k_hist<<<(E + tb - 1) / tb, tb>>>(ei, E);                      // launch 1
    k_scan<<<1, 1024>>>(x, n);                                     // launch 2
    k_scatter_pre<<<(n + E + tb - 1) / tb, tb>>>(ei, E, x, y,      // launch 3
                                                 fc1W, fc1b, fc2W, fc2b, c1W, out, n);

    const int CB_S = 888;   // spmm: 148 SMs x 6 resident blocks -> 48 warps/SM
    const int CB_G = 740;   // gemm: memory-floor, unchanged
    for (int r = 1; r < T; r++) {
        k_spmm<true><<<CB_S, 256>>>(c1W, t, r, n);                            // launch 4 = profiled
        k_gemm<0><<<CB_G, 256>>>(c1b, c2W, nullptr, nullptr, nullptr, nullptr, nullptr, 0, n);
        k_spmm<false><<<CB_S, 256>>>(nullptr, nullptr, 0, n);
        k_gemm<1><<<CB_G, 256>>>(c2b, c3W, nullptr, nullptr, nullptr, nullptr, nullptr, 0, n);
        k_spmm<false><<<CB_S, 256>>>(nullptr, nullptr, 0, n);
        k_gemm<2><<<CB_G, 256>>>(c3b, c1W, fc3W, fc3b, fc4W, fc4b, out, r, n);  // + head
    }
}

// round 13
// speedup vs baseline: 1.3058x; 1.0726x over previous
#include <cuda_runtime.h>
#include <cuda_fp16.h>
#include <cstdint>

#define NN 100000
#define EE 1600000
#define TOTE (NN + EE)

// ---------------- static device scratch (allocation-free, zero-init) ----------------
__device__ int                g_rowptr[NN + 1];
__device__ int                g_cnt[NN];          // histogram; reset by k_scan for next replay
__device__ int                g_cur[NN];          // scatter cursor
__device__ float              g_dis[NN];          // rsqrt(deg)
__device__ float2             g_axw[NN];          // {A_hat x, A_hat 1} per node (atomic-built)
__device__ unsigned long long g_edge[TOTE];       // packed {src(int32) | normbits<<32}
__device__ uint4              g_bufA[NN * 4];     // z buffer   (fp16 rows, 64B/node)
__device__ uint4              g_bufB[NN * 4];     // agg buffer (fp16 rows, 64B/node)

__device__ __forceinline__ unsigned long long pack_edge(int c, float w) {
    return (unsigned long long)(unsigned)c |
           ((unsigned long long)__float_as_uint(w) << 32);
}

__device__ __forceinline__ uint32_t packh2(float a, float b) {
    __half2 h = __floats2half2_rn(a, b);
    return *reinterpret_cast<uint32_t*>(&h);
}

__device__ __forceinline__ void mma16816(float c[4], const uint32_t a[4], const uint32_t b[2]) {
    asm volatile("mma.sync.aligned.m16n8k16.row.col.f32.f16.f16.f32 "
                 "{%0,%1,%2,%3},{%4,%5,%6,%7},{%8,%9},{%0,%1,%2,%3};"
                 : "+f"(c[0]), "+f"(c[1]), "+f"(c[2]), "+f"(c[3])
                 : "r"(a[0]), "r"(a[1]), "r"(a[2]), "r"(a[3]), "r"(b[0]), "r"(b[1]));
}

// ---------------- preprocessing ----------------
__global__ void k_hist(const int* __restrict__ ei, int E) {
    int e = blockIdx.x * blockDim.x + threadIdx.x;
    if (e < E) atomicAdd(&g_cnt[ei[E + e]], 1);
}

__global__ void k_scan(const float* __restrict__ x, int n) {
    __shared__ int warpsum[32];
    __shared__ int chunkbase;
    const int tid = threadIdx.x, lane = tid & 31, wid = tid >> 5;
    if (tid == 0) chunkbase = 0;
    __syncthreads();
    for (int base = 0; base < n; base += 1024) {
        int i = base + tid;
        int ecnt = (i < n) ? g_cnt[i] : 0;
        if (i < n) g_cnt[i] = 0;                   // reset for next replay
        int v = ecnt + 1;                          // + self-loop
        int s = v;
#pragma unroll
        for (int d = 1; d < 32; d <<= 1) {
            int t = __shfl_up_sync(0xffffffffu, s, d);
            if (lane >= d) s += t;
        }
        if (lane == 31) warpsum[wid] = s;
        __syncthreads();
        if (wid == 0) {
            int ws = warpsum[lane];
#pragma unroll
            for (int d = 1; d < 32; d <<= 1) {
                int t = __shfl_up_sync(0xffffffffu, ws, d);
                if (lane >= d) ws += t;
            }
            warpsum[lane] = ws;
        }
        __syncthreads();
        int excl = chunkbase + s - v + (wid ? warpsum[wid - 1] : 0);
        if (i < n) {
            g_rowptr[i] = excl;
            float dv = rsqrtf((float)v);
            float dvdv = dv * dv;
            g_dis[i] = dv;
            g_edge[excl] = pack_edge(i, dvdv);     // self-loop edge first in row
            g_cur[i] = excl + 1;
            g_axw[i] = make_float2(dvdv * __ldg(&x[i]), dvdv);  // self-loop seed
        }
        __syncthreads();
        if (tid == 0) chunkbase += warpsum[31];
        __syncthreads();
    }
    if (tid == 0) g_rowptr[n] = chunkbase;
}

// fused: edge scatter (+atomic A_hat x / A_hat 1) AND per-node init producing
// z1 = h_init @ W1a directly (h_init = relu(fc2(relu(fc1(y0))))).
__global__ void k_scatter_pre(const int* __restrict__ ei, int E,
                              const float* __restrict__ x, const float* __restrict__ y,
                              const float* __restrict__ fc1W, const float* __restrict__ fc1b,
                              const float* __restrict__ fc2W, const float* __restrict__ fc2b,
                              const float* __restrict__ c1W,
                              float* __restrict__ out, int n) {
    __shared__ float s1W[32], s1b[32], s2W[32 * 26], s2b[26], sW1a[26 * 32];
    for (int i = threadIdx.x; i < 32; i += blockDim.x) { s1W[i] = fc1W[i]; s1b[i] = fc1b[i]; }
    for (int i = threadIdx.x; i < 32 * 26; i += blockDim.x) { s2W[i] = fc2W[i]; sW1a[i] = c1W[i]; }
    for (int i = threadIdx.x; i < 26; i += blockDim.x) s2b[i] = fc2b[i];
    __syncthreads();
    uint2* bufz = reinterpret_cast<uint2*>(g_bufA);
    int total = n + E;
    int stride = gridDim.x * blockDim.x;
    for (int g = blockIdx.x * blockDim.x + threadIdx.x; g < total; g += stride) {
        if (g < n) {
            int i = g;
            float y0 = y[i];
            out[i] = y0;
            float h0[32];
#pragma unroll
            for (int j = 0; j < 32; j++) h0[j] = fmaxf(fmaf(y0, s1W[j], s1b[j]), 0.f);
            float h26[26];
#pragma unroll
            for (int j = 0; j < 26; j++) {
                float s = s2b[j];
#pragma unroll
                for (int k = 0; k < 32; k++) s = fmaf(h0[k], s2W[k * 26 + j], s);
                h26[j] = fmaxf(s, 0.f);
            }
            float z[32];
#pragma unroll
            for (int j = 0; j < 32; j++) {
                float s = 0.f;
#pragma unroll
                for (int k = 0; k < 26; k++) s = fmaf(h26[k], sW1a[k * 32 + j], s);
                z[j] = s;
            }
#pragma unroll
            for (int q = 0; q < 8; q++) {
                uint2 pk;
                pk.x = packh2(z[4 * q], z[4 * q + 1]);
                pk.y = packh2(z[4 * q + 2], z[4 * q + 3]);
                bufz[i * 8 + q] = pk;
            }
        } else {
            int e = g - n;
            int s = ei[e];
            int d = ei[E + e];
            float w = g_dis[s] * g_dis[d];
            int pos = atomicAdd(&g_cur[d], 1);
            g_edge[pos] = pack_edge(s, w);
            atomicAdd(&g_axw[d].x, w * __ldg(&x[s]));
            atomicAdd(&g_axw[d].y, w);
        }
    }
}

// ---------------- SpMM: agg = A_hat @ z  (raw, no bias/relu) ----------------
// R10 core + SOFTWARE PIPELINE: node i+1's edge preload issues at top of
// iteration i, hiding its ~250cyc latency under node i's gather/reduce.
// CORR (conv1 only): v[j] += ax*wx[j] + (aone*t)*wt[j]  (folded x/t columns)
template <bool CORR>
__global__ __launch_bounds__(256, 5)
void k_spmm(const float* __restrict__ W1, const float* __restrict__ tarr, int trow, int n) {
    constexpr unsigned FULL = 0xffffffffu;
    __shared__ __align__(16) float swx[32], swt[32];
    __shared__ __align__(16) float red[8][128];     // per-warp 4x32 transpose buffer
    const int tid = threadIdx.x, lane = tid & 31, w = tid >> 5;
    if constexpr (CORR) {
        if (tid < 32) {
            swx[tid] = W1[26 * 32 + tid] + W1[27 * 32 + tid] + W1[28 * 32 + tid];
            swt[tid] = W1[29 * 32 + tid] + W1[30 * 32 + tid] + W1[31 * 32 + tid];
        }
        __syncthreads();
    }
    const int eg = lane >> 3, f = lane & 7;
    const uint2* __restrict__ zin = reinterpret_cast<const uint2*>(g_bufA);
    __half2* __restrict__ aggout2 = reinterpret_cast<__half2*>(g_bufB);
    float wxl = 0.f, wtl = 0.f, tval = 0.f;
    if constexpr (CORR) {
        wxl = swx[lane]; wtl = swt[lane];
        tval = __ldg(&tarr[trow]);
    }
    const int gwid = (blockIdx.x * blockDim.x + tid) >> 5;
    const int nw   = (gridDim.x * blockDim.x) >> 5;
    const int CH   = (n + nw - 1) / nw;                // contiguous chunk per warp (<=30!)
    int base = gwid * CH;
    if (base >= n) return;
    int lim = n - base; if (lim > CH) lim = CH;
    int rp = __ldg(&g_rowptr[base + ((lane < lim) ? lane : lim)]);
    float* myred = red[w];

    // ---- pipeline prologue: preload node 0's edges ----
    unsigned long long evN;
    {
        int b0 = __shfl_sync(FULL, rp, 0);
        int e0 = __shfl_sync(FULL, rp, 1);
        int idx = b0 + lane;
        evN = __ldg(&g_edge[(idx < e0) ? idx : e0 - 1]);
    }

    for (int i = 0; i < lim; i++) {
        int beg = __shfl_sync(FULL, rp, i);
        int end = __shfl_sync(FULL, rp, i + 1);
        int deg = end - beg;
        unsigned long long ev = evN;                   // this node's edges (already in flight)

        // ---- issue NEXT node's edge preload immediately (hidden under this node) ----
        if (i + 1 < lim) {
            int nb2 = end;                             // rowptr[i+1] == end
            int ne2 = __shfl_sync(FULL, rp, i + 2);
            int idx = nb2 + lane;
            evN = __ldg(&g_edge[(idx < ne2) ? idx : ne2 - 1]);
        }

        float ew  = __uint_as_float((unsigned)(ev >> 32));
        int  esrc = (int)(unsigned)ev;
        int dlim = (deg < 32) ? deg : 32;

        float2 axw = make_float2(0.f, 0.f);
        if constexpr (CORR) axw = __ldg(&g_axw[base + i]);   // prefetch early

        float4 acc = make_float4(0.f, 0.f, 0.f, 0.f);
        // ---- phase A: 16 edge slots, 4 independent LDGs in flight ----
        uint2 rg[4]; float wg[4];
#pragma unroll
        for (int k = 0; k < 4; k++) {
            int j = eg + k * 4;
            float wgt = __shfl_sync(FULL, ew, j & 31);
            int   src = __shfl_sync(FULL, esrc, j & 31);
            wg[k] = (j < dlim) ? wgt : 0.f;
            rg[k] = __ldg(&zin[src * 8 + f]);      // clamped src: valid row, wgt=0
        }
#pragma unroll
        for (int k = 0; k < 4; k++) {
            float2 p0 = __half22float2(*reinterpret_cast<const __half2*>(&rg[k].x));
            float2 p1 = __half22float2(*reinterpret_cast<const __half2*>(&rg[k].y));
            acc.x = fmaf(wg[k], p0.x, acc.x);
            acc.y = fmaf(wg[k], p0.y, acc.y);
            acc.z = fmaf(wg[k], p1.x, acc.z);
            acc.w = fmaf(wg[k], p1.y, acc.w);
        }
        // ---- phase B: exact, warp-uniform (deg 17..32) ----
        for (int jb = 16; jb < dlim; jb += 4) {
            int j = jb + eg;
            float wgt = __shfl_sync(FULL, ew, j & 31);
            int   src = __shfl_sync(FULL, esrc, j & 31);
            wgt = (j < dlim) ? wgt : 0.f;
            uint2 raw = __ldg(&zin[src * 8 + f]);
            float2 p0 = __half22float2(*reinterpret_cast<const __half2*>(&raw.x));
            float2 p1 = __half22float2(*reinterpret_cast<const __half2*>(&raw.y));
            acc.x = fmaf(wgt, p0.x, acc.x);
            acc.y = fmaf(wgt, p0.y, acc.y);
            acc.z = fmaf(wgt, p1.x, acc.z);
            acc.w = fmaf(wgt, p1.y, acc.w);
        }
        // ---- rare tail: deg > 32 (no warp-sync primitives; divergence OK) ----
        for (int e2 = beg + 32 + eg; e2 < end; e2 += 4) {
            unsigned long long v = __ldg(&g_edge[e2]);
            float wgt = __uint_as_float((unsigned)(v >> 32));
            int   src = (int)(unsigned)v;
            uint2 raw = __ldg(&zin[src * 8 + f]);
            float2 p0 = __half22float2(*reinterpret_cast<const __half2*>(&raw.x));
            float2 p1 = __half22float2(*reinterpret_cast<const __half2*>(&raw.y));
            acc.x = fmaf(wgt, p0.x, acc.x);
            acc.y = fmaf(wgt, p0.y, acc.y);
            acc.z = fmaf(wgt, p1.x, acc.z);
            acc.w = fmaf(wgt, p1.y, acc.w);
        }
        // ---- smem transpose-reduce: STS.128 + 4 LDS + 3 FADD ----
        *reinterpret_cast<float4*>(&myred[(eg * 8 + f) * 4]) = acc;
        __syncwarp();
        float v = myred[lane] + myred[32 + lane] + myred[64 + lane] + myred[96 + lane];
        __syncwarp();                               // protect red[] before next overwrite
        if constexpr (CORR) {
            v = fmaf(axw.x, wxl, fmaf(axw.y * tval, wtl, v));
        }
        // pack feature pairs -> half2; even lanes store 4B each (64B row)
        float vhi = __shfl_down_sync(FULL, v, 1);
        if ((lane & 1) == 0)
            aggout2[(base + i) * 16 + (lane >> 1)] = __floats2half2_rn(v, vhi);
    }
}

// ---------------- GEMM: z = relu(agg + b_prev) @ W~next, 16-node tiles, HMMA ----------
// KIND 0: b1, W2 (32x32). KIND 1: b2, W3 (32x26 padded). KIND 2: b3(26), W1a (26x32 padded)
//         + fused fc3/relu/fc4 head (A-frags ARE h3 -> reused directly).
template <int KIND>
__global__ __launch_bounds__(256)
void k_gemm(const float* __restrict__ bprev, const float* __restrict__ Wn,
            const float* __restrict__ f3W, const float* __restrict__ f3b,
            const float* __restrict__ f4W, const float* __restrict__ f4b,
            float* __restrict__ out, int trow, int n) {
    constexpr unsigned FULL = 0xffffffffu;
    constexpr int BPREV = (KIND == 2) ? 26 : 32;
    __shared__ __align__(16) __half sWt[32 * 40];
    __shared__ __align__(16) __half sW2[32 * 40];
    __shared__ __align__(16) __half sA[8][16 * 40];
    __shared__ __half2 sbh[16];
    __shared__ float sb3[32], sf4[32], sf4b;

    const int tid = threadIdx.x, lane = tid & 31, w = tid >> 5;

    for (int i = tid; i < 1024; i += blockDim.x) {
        int k = i >> 5, j = i & 31;
        float v;
        if constexpr (KIND == 0)      v = Wn[k * 32 + j];
        else if constexpr (KIND == 1) v = (j < 26) ? Wn[k * 26 + j] : 0.f;
        else                          v = (k < 26) ? Wn[k * 32 + j] : 0.f;
        sWt[k * 40 + j] = __float2half(v);
        if constexpr (KIND == 2)
            sW2[k * 40 + j] = __float2half((k < 26) ? f3W[k * 32 + j] : 0.f);
    }
    if (tid < 16) {
        float b0 = (2 * tid < BPREV)     ? bprev[2 * tid]     : 0.f;
        float b1 = (2 * tid + 1 < BPREV) ? bprev[2 * tid + 1] : 0.f;
        sbh[tid] = __floats2half2_rn(b0, b1);
    }
    if constexpr (KIND == 2) {
        if (tid < 32) { sb3[tid] = f3b[tid]; sf4[tid] = f4W[tid]; }
        if (tid == 0) sf4b = f4b[0];
    }
    __syncthreads();

    uint32_t bf[2][4][2], bf2[2][4][2];
    {
        int r = lane & 15;
#pragma unroll
        for (int s = 0; s < 2; s++)
#pragma unroll
            for (int t = 0; t < 4; t++) {
                uint32_t addr = (uint32_t)__cvta_generic_to_shared(&sWt[(s * 16 + r) * 40 + t * 8]);
                asm volatile("ldmatrix.sync.aligned.m8n8.x2.trans.shared.b16 {%0,%1},[%2];"
                             : "=r"(bf[s][t][0]), "=r"(bf[s][t][1]) : "r"(addr));
                if constexpr (KIND == 2) {
                    uint32_t a2 = (uint32_t)__cvta_generic_to_shared(&sW2[(s * 16 + r) * 40 + t * 8]);
                    asm volatile("ldmatrix.sync.aligned.m8n8.x2.trans.shared.b16 {%0,%1},[%2];"
                                 : "=r"(bf2[s][t][0]), "=r"(bf2[s][t][1]) : "r"(a2));
                }
            }
    }
    const int tig = lane & 3, grp = lane >> 2;
    float b3r[8], wf4[8], b4 = 0.f;
    if constexpr (KIND == 2) {
#pragma unroll
        for (int t = 0; t < 4; t++) {
            b3r[t * 2]     = sb3[t * 8 + tig * 2];
            b3r[t * 2 + 1] = sb3[t * 8 + tig * 2 + 1];
            wf4[t * 2]     = sf4[t * 8 + tig * 2];
            wf4[t * 2 + 1] = sf4[t * 8 + tig * 2 + 1];
        }
        b4 = sf4b;
    }

    const uint4* __restrict__ agg4 = g_bufB;
    __half2* __restrict__ zout = reinterpret_cast<__half2*>(g_bufA);
    const int gwid = (blockIdx.x * blockDim.x + tid) >> 5;
    const int nw   = (gridDim.x * blockDim.x) >> 5;
    const uint32_t abase = (uint32_t)__cvta_generic_to_shared(&sA[w][0]);
    const __half2 zero2 = __float2half2_rn(0.f);

    for (int nb = gwid * 16; nb < n; nb += nw * 16) {
        __syncwarp();
        int row = lane >> 1, c = lane & 1;
        int r = nb + row;
        uint4 v0 = make_uint4(0, 0, 0, 0), v1 = make_uint4(0, 0, 0, 0);
        if (r < n) {
            v0 = __ldg(&agg4[r * 4 + 2 * c]);
            v1 = __ldg(&agg4[r * 4 + 2 * c + 1]);
        }
        // A = relu(agg + b_prev), elementwise in half2
        {
            uint32_t* p = &v0.x;
#pragma unroll
            for (int q = 0; q < 4; q++) {
                __half2 h = *reinterpret_cast<__half2*>(&p[q]);
                h = __hmax2(__hadd2(h, sbh[(2 * c) * 4 + q]), zero2);
                p[q] = *reinterpret_cast<uint32_t*>(&h);
            }
            uint32_t* p2 = &v1.x;
#pragma unroll
            for (int q = 0; q < 4; q++) {
                __half2 h = *reinterpret_cast<__half2*>(&p2[q]);
                h = __hmax2(__hadd2(h, sbh[(2 * c + 1) * 4 + q]), zero2);
                p2[q] = *reinterpret_cast<uint32_t*>(&h);
            }
        }
        char* rowbase = reinterpret_cast<char*>(&sA[w][0]) + row * 80;
        *reinterpret_cast<uint4*>(rowbase + (2 * c) * 16)     = v0;
        *reinterpret_cast<uint4*>(rowbase + (2 * c + 1) * 16) = v1;
        __syncwarp();

        uint32_t af[2][4];
#pragma unroll
        for (int s = 0; s < 2; s++) {
            int g2 = lane >> 3;
            uint32_t addr = abase + ((lane & 7) + (g2 & 1) * 8) * 80 + s * 32 + (g2 >> 1) * 16;
            asm volatile("ldmatrix.sync.aligned.m8n8.x4.shared.b16 {%0,%1,%2,%3},[%4];"
                         : "=r"(af[s][0]), "=r"(af[s][1]), "=r"(af[s][2]), "=r"(af[s][3])
                         : "r"(addr));
        }

        float z[4][4];
#pragma unroll
        for (int t = 0; t < 4; t++) { z[t][0] = 0.f; z[t][1] = 0.f; z[t][2] = 0.f; z[t][3] = 0.f; }
#pragma unroll
        for (int s = 0; s < 2; s++)
#pragma unroll
            for (int t = 0; t < 4; t++)
                mma16816(z[t], af[s], bf[s][t]);

        int r0 = nb + grp, r1 = nb + grp + 8;
        bool ok0 = r0 < n, ok1 = r1 < n;
#pragma unroll
        for (int t = 0; t < 4; t++) {
            __half2 p0 = __floats2half2_rn(z[t][0], z[t][1]);
            __half2 p1 = __floats2half2_rn(z[t][2], z[t][3]);
            if (ok0) zout[r0 * 16 + t * 4 + tig] = p0;
            if (ok1) zout[r1 * 16 + t * 4 + tig] = p1;
        }

        if constexpr (KIND == 2) {
            float zz[4][4];
#pragma unroll
            for (int t = 0; t < 4; t++) {
                zz[t][0] = b3r[t * 2];   zz[t][1] = b3r[t * 2 + 1];
                zz[t][2] = b3r[t * 2];   zz[t][3] = b3r[t * 2 + 1];
            }
#pragma unroll
            for (int s = 0; s < 2; s++)
#pragma unroll
                for (int t = 0; t < 4; t++)
                    mma16816(zz[t], af[s], bf2[s][t]);
            float p0 = 0.f, p1 = 0.f;
#pragma unroll
            for (int t = 0; t < 4; t++) {
                p0 = fmaf(fmaxf(zz[t][0], 0.f), wf4[t * 2],     p0);
                p0 = fmaf(fmaxf(zz[t][1], 0.f), wf4[t * 2 + 1], p0);
                p1 = fmaf(fmaxf(zz[t][2], 0.f), wf4[t * 2],     p1);
                p1 = fmaf(fmaxf(zz[t][3], 0.f), wf4[t * 2 + 1], p1);
            }
            p0 += __shfl_xor_sync(FULL, p0, 1);
            p0 += __shfl_xor_sync(FULL, p0, 2);
            p1 += __shfl_xor_sync(FULL, p1, 1);
            p1 += __shfl_xor_sync(FULL, p1, 2);
            if (tig == 0) {
                long long ob = (long long)trow * n;
                if (ok0) out[ob + r0] = p0 + b4;
                if (ok1) out[ob + r1] = p1 + b4;
            }
        }
    }
}

// ---------------- launcher ----------------
extern "C" void kernel_launch(void* const* d_in, const int* in_sizes, int n_in,
                              void* d_out, int out_size) {
    const float* x    = (const float*)d_in[0];
    const float* t    = (const float*)d_in[1];
    const float* y    = (const float*)d_in[2];
    const int*   ei   = (const int*)d_in[3];     // int32 (JAX x64 disabled)
    const float* fc1W = (const float*)d_in[4],  *fc1b = (const float*)d_in[5];
    const float* fc2W = (const float*)d_in[6],  *fc2b = (const float*)d_in[7];
    const float* c1W  = (const float*)d_in[8],  *c1b  = (const float*)d_in[9];
    const float* c2W  = (const float*)d_in[10], *c2b  = (const float*)d_in[11];
    const float* c3W  = (const float*)d_in[12], *c3b  = (const float*)d_in[13];
    const float* fc3W = (const float*)d_in[14], *fc3b = (const float*)d_in[15];
    const float* fc4W = (const float*)d_in[16], *fc4b = (const float*)d_in[17];

    int n = in_sizes[0];          // N
    int T = in_sizes[1];          // timesteps
    int E = in_sizes[3] / 2;      // edges
    float* out = (float*)d_out;

    const int tb = 256;
    k_hist<<<(E + tb - 1) / tb, tb>>>(ei, E);                      // launch 1
    k_scan<<<1, 1024>>>(x, n);                                     // launch 2
    k_scatter_pre<<<(n + E + tb - 1) / tb, tb>>>(ei, E, x, y,      // launch 3
                                                 fc1W, fc1b, fc2W, fc2b, c1W, out, n);

    const int CB_S = 740;   // spmm: R10-proven best grid (5 blocks/SM)
    const int CB_G = 740;   // gemm: memory-floor, unchanged
    for (int r = 1; r < T; r++) {
        k_spmm<true><<<CB_S, 256>>>(c1W, t, r, n);                            // launch 4 = profiled
        k_gemm<0><<<CB_G, 256>>>(c1b, c2W, nullptr, nullptr, nullptr, nullptr, nullptr, 0, n);
        k_spmm<false><<<CB_S, 256>>>(nullptr, nullptr, 0, n);
        k_gemm<1><<<CB_G, 256>>>(c2b, c3W, nullptr, nullptr, nullptr, nullptr, nullptr, 0, n);
        k_spmm<false><<<CB_S, 256>>>(nullptr, nullptr, 0, n);
        k_gemm<2><<<CB_G, 256>>>(c3b, c1W, fc3W, fc3b, fc4W, fc4b, out, r, n);  // + head
    }
}